// round 5
// baseline (speedup 1.0000x reference)
#include <cuda_runtime.h>
#include <math.h>

#define B_  64
#define LQ  32
#define O_  128
#define LK  256
#define D_  128
#define FULLM 0xffffffffu

// Scratch (device globals)
__device__ float g_invq[B_ * LQ];
__device__ float g_invk[O_ * LK];
__device__ int   g_q_active[B_];
__device__ int   g_mask_mode;          // 0=int32, 1=uint8, 2=float32

__device__ __forceinline__ bool mask_at(const void* buf, int idx, int mode) {
    if (mode == 0) return ((const int*)buf)[idx] != 0;
    if (mode == 2) return ((const float*)buf)[idx] != 0.0f;
    return ((const unsigned char*)buf)[idx] != 0;
}

// ---- f32x2 packed helpers -------------------------------------------------
__device__ __forceinline__ unsigned long long pk2(float a, float b) {
    unsigned long long r;
    asm("mov.b64 %0,{%1,%2};" : "=l"(r) : "f"(a), "f"(b));
    return r;
}
__device__ __forceinline__ void fma2(unsigned long long& d,
                                     unsigned long long a, unsigned long long b) {
    asm("fma.rn.f32x2 %0,%1,%2,%0;" : "+l"(d) : "l"(a), "l"(b));
}
__device__ __forceinline__ float2 upk2(unsigned long long v) {
    float2 r;
    asm("mov.b64 {%0,%1},%2;" : "=f"(r.x), "=f"(r.y) : "l"(v));
    return r;
}

// ---------------------------------------------------------------------------
// Kernel 1: inverse L2 norms (warp per 128-float row).
// ---------------------------------------------------------------------------
__global__ void invnorm_kernel(const float* __restrict__ q,
                               const float* __restrict__ k) {
    int gw   = (blockIdx.x * blockDim.x + threadIdx.x) >> 5;
    int lane = threadIdx.x & 31;
    const int nq = B_ * LQ;
    if (gw >= nq + O_ * LK) return;
    const float* src = (gw < nq) ? q : k;
    int row = (gw < nq) ? gw : gw - nq;
    float4 v = ((const float4*)(src + (size_t)row * D_))[lane];
    float ss = v.x * v.x + v.y * v.y + v.z * v.z + v.w * v.w;
    #pragma unroll
    for (int o = 16; o; o >>= 1) ss += __shfl_xor_sync(FULLM, ss, o);
    if (lane == 0) {
        float inv = 1.0f / fmaxf(sqrtf(ss), 1e-12f);
        if (gw < nq) g_invq[row] = inv; else g_invk[row] = inv;
    }
}

// ---------------------------------------------------------------------------
// Kernel 2: mask-dtype sniff + per-batch active flag + zero out.
// Each block redundantly sniffs the first 2048 BYTES of q_mask (safe for
// uint8/int32/f32 buffers) so no separate detect launch is needed.
// ---------------------------------------------------------------------------
__global__ void qactive_kernel(const unsigned int* __restrict__ qm_words,
                               float* __restrict__ out) {
    int b = blockIdx.x, l = threadIdx.x;
    bool ok_i32 = true, ok_f32 = true;
    for (int i = l; i < 512; i += 32) {
        unsigned int w = qm_words[i];
        if (w > 1u) ok_i32 = false;
        if (w != 0u && w != 0x3F800000u) ok_f32 = false;
    }
    unsigned bi = __ballot_sync(FULLM, ok_i32);
    unsigned bf = __ballot_sync(FULLM, ok_f32);
    int mode = (bi == FULLM) ? 0 : (bf == FULLM) ? 2 : 1;
    if (b == 0 && l == 0) g_mask_mode = mode;

    bool m = mask_at((const void*)qm_words, b * LQ + l, mode);
    unsigned bal = __ballot_sync(FULLM, m);
    if (l == 0) g_q_active[b] = (bal == 0u) ? 1 : 0;

    // zero out[64*128]: 64 blocks * 32 threads * 4 floats
    ((float4*)out)[b * 32 + l] = make_float4(0.f, 0.f, 0.f, 0.f);
}

// ---------------------------------------------------------------------------
// Kernel 3: score. Block = (o, b, ihalf). 128 threads = 4 warps.
// Warp w: jhalf = w>>1 (j base 0 / 128), ihw = w&1 (8 i rows each).
// Lane l owns j = jhalf*128 + 4l .. +3. fp32x2 packed accumulators.
// k chunk (32 d) transposed to smem kt[d][j] with granule swizzle
// (verified conflict-free on STS scatter and LDS.128 reads in R4).
// Partial score (16 i rows) atomically added to out (exactly 2 adders).
// ---------------------------------------------------------------------------
__global__ __launch_bounds__(128, 5)
void score_kernel(const float* __restrict__ q,
                  const float* __restrict__ k,
                  const void* __restrict__ k_mask,
                  const float* __restrict__ logit_scale,
                  float* __restrict__ out) {
    const int o     = blockIdx.x;
    const int b     = blockIdx.y;
    const int ihalf = blockIdx.z;
    const int tid   = threadIdx.x;

    if (!g_q_active[b]) return;           // out already zeroed

    extern __shared__ float smem[];
    float* q_s   = smem;                  // 16*128 = 2048
    float* kt    = q_s + 16 * D_;         // 32*256 = 8192 (swizzled)
    float* ivk_s = kt + 32 * LK;          // 256
    float* wm_s  = ivk_s + LK;            // 256
    float* ivq_s = wm_s + LK;             // 16
    float* red   = ivq_s + 16;            // 32  (16 i x 2 jhalf)

    // Stage q half-tile [16][128]
    {
        const float4* q4 = (const float4*)(q + (size_t)b * LQ * D_ + ihalf * 16 * D_);
        #pragma unroll
        for (int it = 0; it < 4; it++)
            ((float4*)q_s)[it * 128 + tid] = q4[it * 128 + tid];
    }
    if (tid < 16) ivq_s[tid] = g_invq[b * LQ + ihalf * 16 + tid];
    {
        int mode = g_mask_mode;
        #pragma unroll
        for (int r = 0; r < 2; r++) {
            int j = r * 128 + tid;
            ivk_s[j] = g_invk[o * LK + j];
            wm_s[j]  = mask_at(k_mask, o * LK + j, mode) ? 0.0f : 1.0f;
        }
    }

    const int w = tid >> 5, l = tid & 31;
    const int jhalf = w >> 1, ihw = (w & 1) * 8;

    unsigned long long acc[8][2];
    #pragma unroll
    for (int ii = 0; ii < 8; ii++) { acc[ii][0] = 0ull; acc[ii][1] = 0ull; }

    const float4* kr4 = (const float4*)(k + (size_t)o * LK * D_);

    #pragma unroll 1
    for (int c = 0; c < 4; c++) {         // 4 chunks of 32 d
        __syncthreads();
        // Coalesced load + swizzled transpose: 16 iters x 16 j, d4 = tid&7.
        #pragma unroll
        for (int t = 0; t < 16; t++) {
            int j  = t * 16 + (tid >> 3);
            int d4 = tid & 7;
            float4 v = kr4[j * (D_ / 4) + c * 8 + d4];
            int col = (((j >> 2) ^ d4) << 2) + (j & 3);
            kt[(4 * d4 + 0) * LK + col] = v.x;
            kt[(4 * d4 + 1) * LK + col] = v.y;
            kt[(4 * d4 + 2) * LK + col] = v.z;
            kt[(4 * d4 + 3) * LK + col] = v.w;
        }
        __syncthreads();

        #pragma unroll 4
        for (int d2 = 0; d2 < 16; d2++) { // 2 d per step
            int d0 = 2 * d2;
            unsigned long long kp0[2], kp1[2];
            {
                int s0 = (d0 >> 2) & 7;
                const float* r0 = kt + d0 * LK + jhalf * 128;
                float4 a = *(const float4*)(r0 + ((l ^ s0) << 2));
                kp0[0] = pk2(a.x, a.y); kp0[1] = pk2(a.z, a.w);
                int s1 = ((d0 + 1) >> 2) & 7;
                const float* r1 = kt + (d0 + 1) * LK + jhalf * 128;
                float4 c1 = *(const float4*)(r1 + ((l ^ s1) << 2));
                kp1[0] = pk2(c1.x, c1.y); kp1[1] = pk2(c1.z, c1.w);
            }
            #pragma unroll
            for (int ii = 0; ii < 8; ii++) {
                float2 qv = *(const float2*)(q_s + (ihw + ii) * D_ + c * 32 + d0);
                unsigned long long qd0 = pk2(qv.x, qv.x);
                unsigned long long qd1 = pk2(qv.y, qv.y);
                fma2(acc[ii][0], qd0, kp0[0]);
                fma2(acc[ii][1], qd0, kp0[1]);
                fma2(acc[ii][0], qd1, kp1[0]);
                fma2(acc[ii][1], qd1, kp1[1]);
            }
        }
    }

    // Epilogue: per-lane partial p_i over its 8 j (within jhalf), warp-reduce.
    float4 iva = *(const float4*)(ivk_s + jhalf * 128 + 4 * l);
    float4 wma = *(const float4*)(wm_s + jhalf * 128 + 4 * l);
    #pragma unroll
    for (int ii = 0; ii < 8; ii++) {
        float a12 = 12.0f * ivq_s[ihw + ii];
        float2 f0 = upk2(acc[ii][0]), f1 = upk2(acc[ii][1]);
        float p = wma.x * __expf(a12 * iva.x * f0.x)
                + wma.y * __expf(a12 * iva.y * f0.y)
                + wma.z * __expf(a12 * iva.z * f1.x)
                + wma.w * __expf(a12 * iva.w * f1.y);
        #pragma unroll
        for (int of = 16; of; of >>= 1) p += __shfl_xor_sync(FULLM, p, of);
        if (l == 0) red[(ihw + ii) * 2 + jhalf] = p;
    }
    __syncthreads();

    if (tid < 16) {
        float p = red[tid * 2] + red[tid * 2 + 1];   // full 256-j sum
        float lse = __logf(p);                        // -inf if all masked
        #pragma unroll
        for (int of = 8; of; of >>= 1)
            lse += __shfl_xor_sync(0xffffu, lse, of);
        if (tid == 0) {
            float s = lse * (1.0f / 12.0f);
            s = s / (sqrtf((float)(LQ * LK)) + 1e-6f);
            s *= fminf(expf(logit_scale[0]), 100.0f);
            atomicAdd(out + b * O_ + o, s);           // 2 adders: deterministic
        }
    }
}

// ---------------------------------------------------------------------------
// Kernel 4: finalize — non-finite scores become 0 (matches reference).
// ---------------------------------------------------------------------------
__global__ void finalize_kernel(float* __restrict__ out) {
    int i = blockIdx.x * blockDim.x + threadIdx.x;
    float v = out[i];
    if (!isfinite(v)) out[i] = 0.0f;
}

// ---------------------------------------------------------------------------
extern "C" void kernel_launch(void* const* d_in, const int* in_sizes, int n_in,
                              void* d_out, int out_size) {
    const float* q  = (const float*)d_in[0];
    const float* k  = (const float*)d_in[1];
    const void*  qm = d_in[2];
    const void*  km = d_in[3];
    const float* ls = (const float*)d_in[4];
    float* out = (float*)d_out;

    {
        int nrows = B_ * LQ + O_ * LK;
        invnorm_kernel<<<(nrows + 7) / 8, 256>>>(q, k);
    }
    qactive_kernel<<<B_, 32>>>((const unsigned int*)qm, out);

    {
        const int smem_bytes =
            (16 * D_ + 32 * LK + LK + LK + 16 + 32) * (int)sizeof(float);
        cudaFuncSetAttribute(score_kernel,
                             cudaFuncAttributeMaxDynamicSharedMemorySize,
                             smem_bytes);
        dim3 grid(O_, B_, 2);
        score_kernel<<<grid, 128, smem_bytes>>>(q, k, km, ls, out);
    }
    finalize_kernel<<<(B_ * O_) / 256, 256>>>(out);
}

// round 7
// speedup vs baseline: 1.4994x; 1.4994x over previous
#include <cuda_runtime.h>
#include <math.h>

#define B_  64
#define LQ  32
#define O_  128
#define LK  256
#define D_  128
#define FULLM 0xffffffffu

__device__ __forceinline__ bool mask_at(const void* buf, int idx, int mode) {
    if (mode == 0) return ((const int*)buf)[idx] != 0;
    if (mode == 2) return ((const float*)buf)[idx] != 0.0f;
    return ((const unsigned char*)buf)[idx] != 0;
}

// ---- f32x2 packed helpers -------------------------------------------------
__device__ __forceinline__ unsigned long long pk2(float a, float b) {
    unsigned long long r;
    asm("mov.b64 %0,{%1,%2};" : "=l"(r) : "f"(a), "f"(b));
    return r;
}
__device__ __forceinline__ void fma2(unsigned long long& d,
                                     unsigned long long a, unsigned long long b) {
    asm("fma.rn.f32x2 %0,%1,%2,%0;" : "+l"(d) : "l"(a), "l"(b));
}
__device__ __forceinline__ float2 upk2(unsigned long long v) {
    float2 r;
    asm("mov.b64 {%0,%1},%2;" : "=f"(r.x), "=f"(r.y) : "l"(v));
    return r;
}

// ---------------------------------------------------------------------------
// Single fused kernel. Block = (o, b), 256 threads = 8 warps.
//   Phase A: mask-dtype sniff + q-activity; inactive -> write 0, exit (~400cy).
//   Phase B: stage q [32][128]; invq from staged tile; k-mask weights.
//   Phase C: 4 chunks of 32 d: coalesced k load -> swizzled smem transpose
//            (ksq accumulated in-flight for invk), fp32x2 FMA mainloop.
//            Warp w: jhalf=w&1 (j base 0/128), i rows [(w>>1)*8, +8).
//            Lane l owns j = jhalf*128 + 4l..4l+3.
//   Phase D: invk from ksq octet-reduction; epilogue lse + final score.
// Swizzle (verified): store col = ((j>>2)^d4)<<2 | (j&3); per-warp j>>2 is
// constant and d4 spans 0..7 -> 32 distinct banks on STS; reads use granule
// l^s0 (s0=row>>2) -> XOR-permutation, conflict-free LDS.128, retrieves j=4l.
// ---------------------------------------------------------------------------
__global__ __launch_bounds__(256, 2)
void fused_score_kernel(const float* __restrict__ q,
                        const float* __restrict__ k,
                        const void* __restrict__ q_mask,
                        const void* __restrict__ k_mask,
                        const float* __restrict__ logit_scale,
                        float* __restrict__ out) {
    const int o   = blockIdx.x;
    const int b   = blockIdx.y;
    const int tid = threadIdx.x;
    const int w   = tid >> 5, l = tid & 31;

    __shared__ int s_mode, s_active;
    extern __shared__ float smem[];
    float* q_s  = smem;              // 4096
    float* kt   = q_s + LQ * D_;     // 8192 (swizzled [d][j] chunk)
    float* ivk  = kt + 32 * LK;      // 256
    float* wm   = ivk + LK;          // 256
    float* ivq  = wm + LK;           // 32
    float* red  = ivq + LQ;          // 64

    // ---- Phase A: sniff + activity (warp 0), fast exit ----
    if (w == 0) {
        unsigned word = ((const unsigned*)q_mask)[l];   // first 128B: safe all dtypes
        unsigned bi = __ballot_sync(FULLM, word <= 1u);
        unsigned bf = __ballot_sync(FULLM, word == 0u || word == 0x3F800000u);
        int mode = (bi == FULLM) ? 0 : (bf == FULLM) ? 2 : 1;
        bool m = mask_at(q_mask, b * LQ + l, mode);
        unsigned bal = __ballot_sync(FULLM, m);
        if (l == 0) { s_mode = mode; s_active = (bal == 0u); }
    }
    __syncthreads();
    if (!s_active) {                  // lse sum = -inf -> score exactly 0
        if (tid == 0) out[b * O_ + o] = 0.0f;
        return;
    }
    const int mode = s_mode;

    // ---- Phase B: stage q, k-mask weights, invq ----
    {
        const float4* q4 = (const float4*)(q + (size_t)b * LQ * D_);
        #pragma unroll
        for (int it = 0; it < 4; it++)
            ((float4*)q_s)[it * 256 + tid] = q4[it * 256 + tid];
        wm[tid] = mask_at(k_mask, o * LK + tid, mode) ? 0.0f : 1.0f;
    }
    __syncthreads();
    {   // warp w computes invq for rows w*4 .. w*4+3
        #pragma unroll
        for (int r = 0; r < 4; r++) {
            int row = w * 4 + r;
            float s = q_s[row * D_ + l] * q_s[row * D_ + l]
                    + q_s[row * D_ + l + 32] * q_s[row * D_ + l + 32]
                    + q_s[row * D_ + l + 64] * q_s[row * D_ + l + 64]
                    + q_s[row * D_ + l + 96] * q_s[row * D_ + l + 96];
            #pragma unroll
            for (int of = 16; of; of >>= 1) s += __shfl_xor_sync(FULLM, s, of);
            if (l == 0) ivq[row] = 1.0f / fmaxf(sqrtf(s), 1e-12f);
        }
    }

    // ---- Phase C: mainloop ----
    const int jhalf = w & 1, ihw = (w >> 1) * 8;
    unsigned long long acc[8][2];
    #pragma unroll
    for (int ii = 0; ii < 8; ii++) { acc[ii][0] = 0ull; acc[ii][1] = 0ull; }
    float ksq[8];
    #pragma unroll
    for (int t = 0; t < 8; t++) ksq[t] = 0.0f;

    const float4* kr4 = (const float4*)(k + (size_t)o * LK * D_);
    const int g = tid >> 3, d4 = tid & 7;

    #pragma unroll 1
    for (int c = 0; c < 4; c++) {
        __syncthreads();
        // Coalesced load + swizzled transpose; accumulate ksq in-flight.
        #pragma unroll
        for (int t = 0; t < 8; t++) {
            int j = t * 32 + g;
            float4 v = kr4[j * (D_ / 4) + c * 8 + d4];
            ksq[t] += v.x * v.x + v.y * v.y + v.z * v.z + v.w * v.w;
            int col = (((j >> 2) ^ d4) << 2) + (j & 3);
            kt[(4 * d4 + 0) * LK + col] = v.x;
            kt[(4 * d4 + 1) * LK + col] = v.y;
            kt[(4 * d4 + 2) * LK + col] = v.z;
            kt[(4 * d4 + 3) * LK + col] = v.w;
        }
        __syncthreads();

        #pragma unroll 4
        for (int d2 = 0; d2 < 16; d2++) {
            int d0 = 2 * d2;
            unsigned long long kp0[2], kp1[2];
            {
                int s0 = (d0 >> 2) & 7;
                const float* r0 = kt + d0 * LK + jhalf * 128;
                float4 a = *(const float4*)(r0 + ((l ^ s0) << 2));
                kp0[0] = pk2(a.x, a.y); kp0[1] = pk2(a.z, a.w);
                int s1 = ((d0 + 1) >> 2) & 7;
                const float* r1 = kt + (d0 + 1) * LK + jhalf * 128;
                float4 c1 = *(const float4*)(r1 + ((l ^ s1) << 2));
                kp1[0] = pk2(c1.x, c1.y); kp1[1] = pk2(c1.z, c1.w);
            }
            #pragma unroll
            for (int ii = 0; ii < 8; ii++) {
                float2 qv = *(const float2*)(q_s + (ihw + ii) * D_ + c * 32 + d0);
                unsigned long long qd0 = pk2(qv.x, qv.x);
                unsigned long long qd1 = pk2(qv.y, qv.y);
                fma2(acc[ii][0], qd0, kp0[0]);
                fma2(acc[ii][1], qd0, kp0[1]);
                fma2(acc[ii][0], qd1, kp1[0]);
                fma2(acc[ii][1], qd1, kp1[1]);
            }
        }
    }

    // ---- Phase D: invk from ksq, epilogue ----
    #pragma unroll
    for (int t = 0; t < 8; t++) {
        float s = ksq[t];
        s += __shfl_xor_sync(FULLM, s, 1);
        s += __shfl_xor_sync(FULLM, s, 2);
        s += __shfl_xor_sync(FULLM, s, 4);
        if (d4 == 0) ivk[t * 32 + g] = s;       // ssq for row j = t*32+g
    }
    __syncthreads();
    float myinv = 1.0f / fmaxf(sqrtf(ivk[tid]), 1e-12f);
    __syncthreads();
    ivk[tid] = myinv;
    __syncthreads();

    float4 iva = *(const float4*)(ivk + jhalf * 128 + 4 * l);
    float4 wma = *(const float4*)(wm + jhalf * 128 + 4 * l);
    #pragma unroll
    for (int ii = 0; ii < 8; ii++) {
        float a12 = 12.0f * ivq[ihw + ii];
        float2 f0 = upk2(acc[ii][0]), f1 = upk2(acc[ii][1]);
        float p = wma.x * __expf(a12 * iva.x * f0.x)
                + wma.y * __expf(a12 * iva.y * f0.y)
                + wma.z * __expf(a12 * iva.z * f1.x)
                + wma.w * __expf(a12 * iva.w * f1.y);
        #pragma unroll
        for (int of = 16; of; of >>= 1) p += __shfl_xor_sync(FULLM, p, of);
        if (l == 0) red[(ihw + ii) * 2 + jhalf] = p;
    }
    __syncthreads();

    if (tid < 32) {
        float p = red[2 * tid] + red[2 * tid + 1];   // full 256-j weighted sum
        float lse = __logf(p);                        // -inf if all j masked
        #pragma unroll
        for (int of = 16; of; of >>= 1) lse += __shfl_xor_sync(FULLM, lse, of);
        if (tid == 0) {
            float s = lse * (1.0f / 12.0f);
            s = s / (sqrtf((float)(LQ * LK)) + 1e-6f);
            s *= fminf(expf(logit_scale[0]), 100.0f);
            if (!isfinite(s)) s = 0.0f;
            out[b * O_ + o] = s;
        }
    }
}

// ---------------------------------------------------------------------------
extern "C" void kernel_launch(void* const* d_in, const int* in_sizes, int n_in,
                              void* d_out, int out_size) {
    const float* q  = (const float*)d_in[0];
    const float* k  = (const float*)d_in[1];
    const void*  qm = d_in[2];
    const void*  km = d_in[3];
    const float* ls = (const float*)d_in[4];
    float* out = (float*)d_out;

    const int smem_bytes =
        (LQ * D_ + 32 * LK + LK + LK + LQ + 64) * (int)sizeof(float);  // ~51.6KB
    cudaFuncSetAttribute(fused_score_kernel,
                         cudaFuncAttributeMaxDynamicSharedMemorySize,
                         smem_bytes);
    dim3 grid(O_, B_);
    fused_score_kernel<<<grid, 256, smem_bytes>>>(q, k, qm, km, ls, out);
}

// round 9
// speedup vs baseline: 1.6352x; 1.0906x over previous
#include <cuda_runtime.h>
#include <math.h>

#define B_  64
#define LQ  32
#define O_  128
#define LK  256
#define D_  128
#define FULLM 0xffffffffu
#define GRID_N 592        // 4 * 148 SMs

__device__ __forceinline__ bool mask_at(const void* buf, int idx, int mode) {
    if (mode == 0) return ((const int*)buf)[idx] != 0;
    if (mode == 2) return ((const float*)buf)[idx] != 0.0f;
    return ((const unsigned char*)buf)[idx] != 0;
}

// ---- f32x2 packed helpers -------------------------------------------------
__device__ __forceinline__ unsigned long long pk2(float a, float b) {
    unsigned long long r;
    asm("mov.b64 %0,{%1,%2};" : "=l"(r) : "f"(a), "f"(b));
    return r;
}
__device__ __forceinline__ void fma2(unsigned long long& d,
                                     unsigned long long a, unsigned long long b) {
    asm("fma.rn.f32x2 %0,%1,%2,%0;" : "+l"(d) : "l"(a), "l"(b));
}
__device__ __forceinline__ float2 upk2(unsigned long long v) {
    float2 r;
    asm("mov.b64 {%0,%1},%2;" : "=f"(r.x), "=f"(r.y) : "l"(v));
    return r;
}

// ---------------------------------------------------------------------------
// Single kernel, grid = 592 blocks x 256 threads.
//  Phase A: mask-dtype sniff; per-batch active flags (all 64) from q_mask;
//           warp 0 compacts active b's into a list. Blocks 0..63 zero their
//           out row iff inactive (disjoint from compute writes).
//  Phase B: loop over work items (b_active x 128 o's) strided by gridDim:
//           unchanged R7 compute path (swizzled kt transpose, fp32x2 FMA,
//           in-flight ksq for invk, lse epilogue).
// ---------------------------------------------------------------------------
__global__ __launch_bounds__(256, 2)
void fused_score_kernel(const float* __restrict__ q,
                        const float* __restrict__ k,
                        const void* __restrict__ q_mask,
                        const void* __restrict__ k_mask,
                        const float* __restrict__ logit_scale,
                        float* __restrict__ out) {
    const int tid = threadIdx.x;
    const int w   = tid >> 5, l = tid & 31;

    __shared__ int   s_nact;
    __shared__ unsigned char s_blist[B_];
    __shared__ unsigned char s_act[B_];
    extern __shared__ float smem[];
    float* q_s  = smem;              // 4096
    float* kt   = q_s + LQ * D_;     // 8192 (swizzled [d][j] chunk)
    float* ivk  = kt + 32 * LK;      // 256
    float* wm   = ivk + LK;          // 256
    float* ivq  = wm + LK;           // 32
    float* red  = ivq + LQ;          // 64

    // ---- Phase A: mode sniff (per warp, redundant) + active flags ----
    int mode;
    {
        unsigned word = ((const unsigned*)q_mask)[l];   // first 128B safe for all dtypes
        unsigned bi = __ballot_sync(FULLM, word <= 1u);
        unsigned bf = __ballot_sync(FULLM, word == 0u || word == 0x3F800000u);
        mode = (bi == FULLM) ? 0 : (bf == FULLM) ? 2 : 1;
    }
    {
        // thread tid: batch bb = tid>>2, tokens (tid&3)*8 .. +8
        int bb = tid >> 2, sub = tid & 3;
        int any = 0;
        #pragma unroll
        for (int e = 0; e < 8; e++)
            any |= mask_at(q_mask, bb * LQ + sub * 8 + e, mode) ? 1 : 0;
        any |= __shfl_xor_sync(FULLM, any, 1);
        any |= __shfl_xor_sync(FULLM, any, 2);
        if ((l & 3) == 0) s_act[bb] = (any == 0);    // active iff no masked token
    }
    __syncthreads();
    if (w == 0) {       // compact list
        unsigned f0 = __ballot_sync(FULLM, s_act[l] != 0);
        unsigned f1 = __ballot_sync(FULLM, s_act[32 + l] != 0);
        int n0 = __popc(f0);
        if (f0 & (1u << l)) s_blist[__popc(f0 & ((1u << l) - 1u))] = (unsigned char)l;
        if (f1 & (1u << l)) s_blist[n0 + __popc(f1 & ((1u << l) - 1u))] = (unsigned char)(32 + l);
        if (l == 0) s_nact = n0 + __popc(f1);
    }
    // Blocks 0..63: zero out row iff that batch is inactive (no overlap with
    // compute writes, which cover exactly the active rows).
    if (blockIdx.x < B_ && tid < O_) {
        if (!s_act[blockIdx.x]) out[blockIdx.x * O_ + tid] = 0.0f;
    }
    __syncthreads();
    const int n_items = s_nact * O_;

    const int g = tid >> 3, d4 = tid & 7;
    const int jhalf = w & 1, ihw = (w >> 1) * 8;

    // ---- Phase B: work-item loop ----
    for (int item = blockIdx.x; item < n_items; item += GRID_N) {
        const int b = s_blist[item >> 7];
        const int o = item & (O_ - 1);

        // stage q tile + k-mask weights
        {
            const float4* q4 = (const float4*)(q + (size_t)b * LQ * D_);
            #pragma unroll
            for (int it = 0; it < 4; it++)
                ((float4*)q_s)[it * 256 + tid] = q4[it * 256 + tid];
            wm[tid] = mask_at(k_mask, o * LK + tid, mode) ? 0.0f : 1.0f;
        }
        __syncthreads();
        {   // warp w: invq for rows w*4 .. w*4+3
            #pragma unroll
            for (int r = 0; r < 4; r++) {
                int row = w * 4 + r;
                float s = q_s[row * D_ + l] * q_s[row * D_ + l]
                        + q_s[row * D_ + l + 32] * q_s[row * D_ + l + 32]
                        + q_s[row * D_ + l + 64] * q_s[row * D_ + l + 64]
                        + q_s[row * D_ + l + 96] * q_s[row * D_ + l + 96];
                #pragma unroll
                for (int of = 16; of; of >>= 1) s += __shfl_xor_sync(FULLM, s, of);
                if (l == 0) ivq[row] = 1.0f / fmaxf(sqrtf(s), 1e-12f);
            }
        }

        unsigned long long acc[8][2];
        #pragma unroll
        for (int ii = 0; ii < 8; ii++) { acc[ii][0] = 0ull; acc[ii][1] = 0ull; }
        float ksq[8];
        #pragma unroll
        for (int t = 0; t < 8; t++) ksq[t] = 0.0f;

        const float4* kr4 = (const float4*)(k + (size_t)o * LK * D_);

        #pragma unroll 1
        for (int c = 0; c < 4; c++) {
            __syncthreads();
            #pragma unroll
            for (int t = 0; t < 8; t++) {
                int j = t * 32 + g;
                float4 v = kr4[j * (D_ / 4) + c * 8 + d4];
                ksq[t] += v.x * v.x + v.y * v.y + v.z * v.z + v.w * v.w;
                int col = (((j >> 2) ^ d4) << 2) + (j & 3);
                kt[(4 * d4 + 0) * LK + col] = v.x;
                kt[(4 * d4 + 1) * LK + col] = v.y;
                kt[(4 * d4 + 2) * LK + col] = v.z;
                kt[(4 * d4 + 3) * LK + col] = v.w;
            }
            __syncthreads();

            #pragma unroll 4
            for (int d2 = 0; d2 < 16; d2++) {
                int d0 = 2 * d2;
                unsigned long long kp0[2], kp1[2];
                {
                    int s0 = (d0 >> 2) & 7;
                    const float* r0 = kt + d0 * LK + jhalf * 128;
                    float4 a = *(const float4*)(r0 + ((l ^ s0) << 2));
                    kp0[0] = pk2(a.x, a.y); kp0[1] = pk2(a.z, a.w);
                    int s1 = ((d0 + 1) >> 2) & 7;
                    const float* r1 = kt + (d0 + 1) * LK + jhalf * 128;
                    float4 c1 = *(const float4*)(r1 + ((l ^ s1) << 2));
                    kp1[0] = pk2(c1.x, c1.y); kp1[1] = pk2(c1.z, c1.w);
                }
                #pragma unroll
                for (int ii = 0; ii < 8; ii++) {
                    float2 qv = *(const float2*)(q_s + (ihw + ii) * D_ + c * 32 + d0);
                    unsigned long long qd0 = pk2(qv.x, qv.x);
                    unsigned long long qd1 = pk2(qv.y, qv.y);
                    fma2(acc[ii][0], qd0, kp0[0]);
                    fma2(acc[ii][1], qd0, kp0[1]);
                    fma2(acc[ii][0], qd1, kp1[0]);
                    fma2(acc[ii][1], qd1, kp1[1]);
                }
            }
        }

        // invk from ksq (octet reduce), then epilogue
        #pragma unroll
        for (int t = 0; t < 8; t++) {
            float s = ksq[t];
            s += __shfl_xor_sync(FULLM, s, 1);
            s += __shfl_xor_sync(FULLM, s, 2);
            s += __shfl_xor_sync(FULLM, s, 4);
            if (d4 == 0) ivk[t * 32 + g] = s;
        }
        __syncthreads();
        float myinv = 1.0f / fmaxf(sqrtf(ivk[tid]), 1e-12f);
        __syncthreads();
        ivk[tid] = myinv;
        __syncthreads();

        float4 iva = *(const float4*)(ivk + jhalf * 128 + 4 * l);
        float4 wma = *(const float4*)(wm + jhalf * 128 + 4 * l);
        #pragma unroll
        for (int ii = 0; ii < 8; ii++) {
            float a12 = 12.0f * ivq[ihw + ii];
            float2 f0 = upk2(acc[ii][0]), f1 = upk2(acc[ii][1]);
            float p = wma.x * __expf(a12 * iva.x * f0.x)
                    + wma.y * __expf(a12 * iva.y * f0.y)
                    + wma.z * __expf(a12 * iva.z * f1.x)
                    + wma.w * __expf(a12 * iva.w * f1.y);
            #pragma unroll
            for (int of = 16; of; of >>= 1) p += __shfl_xor_sync(FULLM, p, of);
            if (l == 0) red[(ihw + ii) * 2 + jhalf] = p;
        }
        __syncthreads();

        if (tid < 32) {
            float p = red[2 * tid] + red[2 * tid + 1];
            float lse = __logf(p);                    // -inf if all j masked
            #pragma unroll
            for (int of = 16; of; of >>= 1) lse += __shfl_xor_sync(FULLM, lse, of);
            if (tid == 0) {
                float s = lse * (1.0f / 12.0f);
                s = s / (sqrtf((float)(LQ * LK)) + 1e-6f);
                s *= fminf(expf(logit_scale[0]), 100.0f);
                if (!isfinite(s)) s = 0.0f;
                out[b * O_ + o] = s;
            }
        }
        __syncthreads();   // protect smem reuse across items
    }
}

// ---------------------------------------------------------------------------
extern "C" void kernel_launch(void* const* d_in, const int* in_sizes, int n_in,
                              void* d_out, int out_size) {
    const float* q  = (const float*)d_in[0];
    const float* k  = (const float*)d_in[1];
    const void*  qm = d_in[2];
    const void*  km = d_in[3];
    const float* ls = (const float*)d_in[4];
    float* out = (float*)d_out;

    const int smem_bytes =
        (LQ * D_ + 32 * LK + LK + LK + LQ + 64) * (int)sizeof(float);  // ~51.6KB
    cudaFuncSetAttribute(fused_score_kernel,
                         cudaFuncAttributeMaxDynamicSharedMemorySize,
                         smem_bytes);
    fused_score_kernel<<<GRID_N, 256, smem_bytes>>>(q, k, qm, km, ls, out);
}